// round 6
// baseline (speedup 1.0000x reference)
#include <cuda_runtime.h>
#include <math.h>
#include <stdint.h>

#define LSQ   8192
#define EDIM  300
#define HDIM  256
#define G3    768
#define GRU_CLUSTER 8

typedef unsigned long long ull;

// ---------------- scratch (static device allocations; no cudaMalloc) -------
__device__ float g_gx  [LSQ * G3];
__device__ float g_HS  [LSQ * HDIM];
__device__ float g_hsg [LSQ * HDIM];
__device__ float g_hsgT[HDIM * LSQ];
__device__ float g_A   [LSQ * HDIM];
__device__ float g_S   [67108864];        // 8192*8192
__device__ float g_rinv[LSQ];
__device__ float g_hapo[LSQ * HDIM];
__device__ float g_cat [LSQ * 2 * HDIM];
__device__ float g_htil[LSQ * HDIM];
__device__ float g_feat[LSQ * 3 * HDIM];
__device__ float g_hcs [LSQ * HDIM];
__device__ float g_e   [LSQ];
__device__ float g_red [2];
__device__ float g_hc  [HDIM];
__device__ float g_c0  [1];
__device__ float g_cvec[HDIM];
__device__ float g_hcS [HDIM];

// ---------------- helpers --------------------------------------------------
__device__ __forceinline__ float sigm(float x) { return 1.f / (1.f + __expf(-x)); }
__device__ __forceinline__ float tanh_fast(float x) {
    float e = __expf(-2.f * x);
    return (1.f - e) / (1.f + e);
}
__device__ __forceinline__ float warp_sum(float v) {
    #pragma unroll
    for (int o = 16; o; o >>= 1) v += __shfl_xor_sync(0xffffffffu, v, o);
    return v;
}
__device__ __forceinline__ float warp_max(float v) {
    #pragma unroll
    for (int o = 16; o; o >>= 1) v = fmaxf(v, __shfl_xor_sync(0xffffffffu, v, o));
    return v;
}
__device__ __forceinline__ uint32_t smem_u32(const void* p) {
    return (uint32_t)__cvta_generic_to_shared(p);
}
__device__ __forceinline__ void mbar_wait_cluster(uint32_t addr, int parity) {
    asm volatile(
        "{\n\t"
        ".reg .pred P;\n\t"
        "WL_%=:\n\t"
        "mbarrier.try_wait.parity.acquire.cluster.shared::cta.b64 P, [%0], %1, 0x989680;\n\t"
        "@P bra.uni WD_%=;\n\t"
        "bra.uni WL_%=;\n\t"
        "WD_%=:\n\t"
        "}"
        :: "r"(addr), "r"(parity) : "memory");
}

// packed f32x2 ops
#define FMA2(d, a, b)  asm("fma.rn.f32x2 %0, %1, %2, %0;" : "+l"(d) : "l"(a), "l"(b))
#define ADD2(d, a, b)  asm("add.rn.f32x2 %0, %1, %2;" : "=l"(d) : "l"(a), "l"(b))
#define PACK2(d, lo, hi)   asm("mov.b64 %0, {%1, %2};" : "=l"(d) : "f"(lo), "f"(hi))
#define UNPACK2(lo, hi, s) asm("mov.b64 {%0, %1}, %2;" : "=f"(lo), "=f"(hi) : "l"(s))
#define LDS_2U64(a, b, addr) \
    asm volatile("ld.shared.v2.b64 {%0, %1}, [%2];" : "=l"(a), "=l"(b) : "r"(addr))

// ---------------- dummy: shifts ncu capture window (index 3 = gru) ---------
__global__ void dummy_kernel() {}

// ---------------- pipelined f32x2 SGEMM: C = act(rscale[m]*(A@B^T)+bias[n])
template <int ACT>
__global__ void __launch_bounds__(256)
sgemm_db(const float* __restrict__ A, int lda,
         const float* __restrict__ B, int ldb,
         float* __restrict__ C, int ldc,
         int M, int N, int K,
         const float* __restrict__ bias,
         const float* __restrict__ rscale)
{
    __shared__ float As[2][8][128];
    __shared__ float Bs[2][8][128];
    const int bm = blockIdx.y * 128, bn = blockIdx.x * 128;
    const int tid = threadIdx.x;
    const int ty = tid >> 4, tx = tid & 15;
    const int lr = tid >> 1;
    const int lc4 = (tid & 1) * 4;
    const int KT = K >> 3;

    const float* Aptr = A + (size_t)(bm + lr) * lda + lc4;
    const float* Bptr = B + (size_t)(bn + lr) * ldb + lc4;

    float4 ra = *(const float4*)Aptr;
    float4 rb = *(const float4*)Bptr;
    As[0][lc4 + 0][lr] = ra.x; As[0][lc4 + 1][lr] = ra.y;
    As[0][lc4 + 2][lr] = ra.z; As[0][lc4 + 3][lr] = ra.w;
    Bs[0][lc4 + 0][lr] = rb.x; Bs[0][lc4 + 1][lr] = rb.y;
    Bs[0][lc4 + 2][lr] = rb.z; Bs[0][lc4 + 3][lr] = rb.w;
    if (KT > 1) { ra = *(const float4*)(Aptr + 8); rb = *(const float4*)(Bptr + 8); }
    __syncthreads();

    ull acc[8][4];
    #pragma unroll
    for (int i = 0; i < 8; i++)
        #pragma unroll
        for (int j = 0; j < 4; j++) acc[i][j] = 0ull;

    const uint32_t asb = smem_u32(&As[0][0][0]);
    const uint32_t bsb = smem_u32(&Bs[0][0][0]);

    for (int kt = 0; kt < KT; kt++) {
        const int buf = kt & 1;
        if (kt + 1 < KT) {
            const int nb = buf ^ 1;
            As[nb][lc4 + 0][lr] = ra.x; As[nb][lc4 + 1][lr] = ra.y;
            As[nb][lc4 + 2][lr] = ra.z; As[nb][lc4 + 3][lr] = ra.w;
            Bs[nb][lc4 + 0][lr] = rb.x; Bs[nb][lc4 + 1][lr] = rb.y;
            Bs[nb][lc4 + 2][lr] = rb.z; Bs[nb][lc4 + 3][lr] = rb.w;
        }
        if (kt + 2 < KT) {
            ra = *(const float4*)(Aptr + (size_t)(kt + 2) * 8);
            rb = *(const float4*)(Bptr + (size_t)(kt + 2) * 8);
        }
        const uint32_t aoff = asb + (uint32_t)(buf * 4096 + ty * 32);
        const uint32_t boff = bsb + (uint32_t)(buf * 4096 + tx * 32);
        #pragma unroll
        for (int kk = 0; kk < 8; kk++) {
            ull b0, b1, b2, b3;
            LDS_2U64(b0, b1, boff + kk * 512);
            LDS_2U64(b2, b3, boff + kk * 512 + 16);
            float4 av0 = *(const float4*)((const char*)As + (aoff - asb) + kk * 512);
            float4 av1 = *(const float4*)((const char*)As + (aoff - asb) + kk * 512 + 16);
            ull a2[8];
            PACK2(a2[0], av0.x, av0.x); PACK2(a2[1], av0.y, av0.y);
            PACK2(a2[2], av0.z, av0.z); PACK2(a2[3], av0.w, av0.w);
            PACK2(a2[4], av1.x, av1.x); PACK2(a2[5], av1.y, av1.y);
            PACK2(a2[6], av1.z, av1.z); PACK2(a2[7], av1.w, av1.w);
            #pragma unroll
            for (int i = 0; i < 8; i++) {
                FMA2(acc[i][0], a2[i], b0);
                FMA2(acc[i][1], a2[i], b1);
                FMA2(acc[i][2], a2[i], b2);
                FMA2(acc[i][3], a2[i], b3);
            }
        }
        __syncthreads();
    }

    float4 bz0 = make_float4(0.f, 0.f, 0.f, 0.f), bz1 = bz0;
    if (bias) {
        bz0 = *(const float4*)&bias[bn + tx * 8];
        bz1 = *(const float4*)&bias[bn + tx * 8 + 4];
    }
    #pragma unroll
    for (int i = 0; i < 8; i++) {
        const int m = bm + ty * 8 + i;
        const float rs = rscale ? rscale[m] : 1.f;
        float4 o0, o1;
        UNPACK2(o0.x, o0.y, acc[i][0]); UNPACK2(o0.z, o0.w, acc[i][1]);
        UNPACK2(o1.x, o1.y, acc[i][2]); UNPACK2(o1.z, o1.w, acc[i][3]);
        o0.x = o0.x * rs + bz0.x; o0.y = o0.y * rs + bz0.y;
        o0.z = o0.z * rs + bz0.z; o0.w = o0.w * rs + bz0.w;
        o1.x = o1.x * rs + bz1.x; o1.y = o1.y * rs + bz1.y;
        o1.z = o1.z * rs + bz1.z; o1.w = o1.w * rs + bz1.w;
        if (ACT == 1) {
            o0.x = tanh_fast(o0.x); o0.y = tanh_fast(o0.y);
            o0.z = tanh_fast(o0.z); o0.w = tanh_fast(o0.w);
            o1.x = tanh_fast(o1.x); o1.y = tanh_fast(o1.y);
            o1.z = tanh_fast(o1.z); o1.w = tanh_fast(o1.w);
        }
        float* cp = C + (size_t)m * ldc + bn + tx * 8;
        *(float4*)cp = o0;
        *(float4*)(cp + 4) = o1;
    }
}

// ---------------- fallback SGEMM for K=300 (gx projection) -----------------
__global__ void __launch_bounds__(256)
sgemm128(const float* __restrict__ A, int lda,
         const float* __restrict__ B, int ldb,
         float* __restrict__ C, int ldc,
         int M, int N, int K,
         const float* __restrict__ bias)
{
    __shared__ float As[8][128];
    __shared__ float Bs[8][128];
    const int bm = blockIdx.y * 128, bn = blockIdx.x * 128;
    const int tid = threadIdx.x;
    const int ty = tid / 16, tx = tid % 16;
    const int lr = tid >> 1;
    const int lc = (tid & 1) * 4;

    float acc[8][8];
    #pragma unroll
    for (int i = 0; i < 8; i++)
        #pragma unroll
        for (int j = 0; j < 8; j++) acc[i][j] = 0.f;

    for (int k0 = 0; k0 < K; k0 += 8) {
        const float* Ap = A + (size_t)(bm + lr) * lda + k0 + lc;
        const float* Bp = B + (size_t)(bn + lr) * ldb + k0 + lc;
        #pragma unroll
        for (int i = 0; i < 4; i++) {
            As[lc + i][lr] = (k0 + lc + i < K) ? Ap[i] : 0.f;
            Bs[lc + i][lr] = (k0 + lc + i < K) ? Bp[i] : 0.f;
        }
        __syncthreads();
        #pragma unroll
        for (int kk = 0; kk < 8; kk++) {
            float4 a0 = *(const float4*)&As[kk][ty * 8];
            float4 a1 = *(const float4*)&As[kk][ty * 8 + 4];
            float4 b0 = *(const float4*)&Bs[kk][tx * 8];
            float4 b1 = *(const float4*)&Bs[kk][tx * 8 + 4];
            float av[8] = {a0.x, a0.y, a0.z, a0.w, a1.x, a1.y, a1.z, a1.w};
            float bv[8] = {b0.x, b0.y, b0.z, b0.w, b1.x, b1.y, b1.z, b1.w};
            #pragma unroll
            for (int i = 0; i < 8; i++)
                #pragma unroll
                for (int j = 0; j < 8; j++)
                    acc[i][j] = fmaf(av[i], bv[j], acc[i][j]);
        }
        __syncthreads();
    }

    #pragma unroll
    for (int i = 0; i < 8; i++) {
        int m = bm + ty * 8 + i;
        #pragma unroll
        for (int j = 0; j < 8; j++) {
            int n = bn + tx * 8 + j;
            C[(size_t)m * ldc + n] = acc[i][j] + (bias ? bias[n] : 0.f);
        }
    }
}

// ---------------- claim GRU (L=1) + c0 + cvec ------------------------------
__global__ void claim_kernel(const float* __restrict__ claim,
                             const float* __restrict__ wih,
                             const float* __restrict__ bih,
                             const float* __restrict__ bhh,
                             const float* __restrict__ gate_c_w,
                             const float* __restrict__ joint_w)
{
    __shared__ float sc[EDIM];
    __shared__ float gx[G3];
    __shared__ float hcs[HDIM];
    int tid = threadIdx.x;  // 768 threads
    for (int k = tid; k < EDIM; k += G3) sc[k] = claim[k];
    __syncthreads();

    float a = 0.f;
    const float* w = wih + (size_t)tid * EDIM;
    for (int k = 0; k < EDIM; k++) a += sc[k] * w[k];
    gx[tid] = a + bih[tid];
    __syncthreads();

    if (tid < HDIM) {
        float r = sigm(gx[tid] + bhh[tid]);
        float z = sigm(gx[HDIM + tid] + bhh[HDIM + tid]);
        float n = tanhf(gx[2 * HDIM + tid] + r * bhh[2 * HDIM + tid]);
        float h = (1.f - z) * n;     // h0 = 0
        hcs[tid] = h;
        g_hc[tid] = h;
    }
    __syncthreads();

    if (tid < 32) {
        float s = 0.f;
        for (int k = tid; k < HDIM; k += 32) s += hcs[k] * gate_c_w[k];
        s = warp_sum(s);
        if (tid == 0) g_c0[0] = s;
    }
    if (tid < HDIM) {
        float s = 0.f;
        const float* jw = joint_w + (size_t)tid * 1024;
        for (int k = 0; k < HDIM; k++) s += hcs[k] * jw[k];
        g_cvec[tid] = s;
    }
}

// ---------------- sentence GRU: 8-CTA cluster, bulk-copy broadcast ---------
// 512 thr/CTA = 16 warps; warp w owns outputs j = rank*32 + 2w + half.
// Per 16-lane half: gate = (lane&15)>>2 in {0:r,1:z,2:n,3:idle}, kslice=lane&3.
// Broadcast: producers stage 32 floats (128B) in smem; lanes 0-7 each issue ONE
// cp.async.bulk (128B) to peer 'tid' -> 8 messages/step, 8 mbarrier tx-updates.
__global__ void __cluster_dims__(GRU_CLUSTER, 1, 1) __launch_bounds__(512, 1)
gru_kernel(const float* __restrict__ whh,
           const float* __restrict__ bhh,
           const float* __restrict__ gx,
           float* __restrict__ HS, int T)
{
    __shared__ __align__(16) float sh_h[2][HDIM];
    __shared__ __align__(16) float stage[32];
    __shared__ __align__(8) unsigned long long mbar2[2];

    const int tid   = threadIdx.x;
    const int lane  = tid & 31;
    const int warp  = tid >> 5;       // 0..15
    const int half  = (lane >> 4);    // 0/1
    const int lane4 = lane & 15;
    const int gate  = lane4 >> 2;     // 0..3 (3 idle)
    const int ksl   = lane4 & 3;
    unsigned rank;
    asm("mov.u32 %0, %%cluster_ctarank;" : "=r"(rank));
    const int jl = warp * 2 + half;               // CTA-local output 0..31
    const int j  = (int)rank * 32 + jl;           // global output 0..255
    const bool prod = (lane4 == 0);

    const uint32_t h_base = smem_u32(&sh_h[0][0]);
    const uint32_t s_base = smem_u32(&stage[0]);
    const uint32_t m_base = smem_u32(&mbar2[0]);

    // per-rank DSMEM bases (receive buffer + mbarrier), computed once
    uint32_t peer_h[GRU_CLUSTER], peer_m[GRU_CLUSTER];
    #pragma unroll
    for (int c = 0; c < GRU_CLUSTER; c++) {
        asm("mapa.shared::cluster.u32 %0, %1, %2;" : "=r"(peer_h[c]) : "r"(h_base), "r"(c));
        asm("mapa.shared::cluster.u32 %0, %1, %2;" : "=r"(peer_m[c]) : "r"(m_base), "r"(c));
    }

    // weights -> 32 packed f32x2 registers
    ull ww[32];
    if (gate < 3) {
        const float4* wp = reinterpret_cast<const float4*>(
            whh + (size_t)(gate * HDIM + j) * HDIM + ksl * 64);
        #pragma unroll
        for (int i = 0; i < 16; i++) {
            float4 v = wp[i];
            PACK2(ww[2 * i],     v.x, v.y);
            PACK2(ww[2 * i + 1], v.z, v.w);
        }
    } else {
        #pragma unroll
        for (int i = 0; i < 32; i++) ww[i] = 0ull;
    }
    const float b_r = bhh[j];
    const float b_z = bhh[HDIM + j];
    const float b_n = bhh[2 * HDIM + j];

    if (tid < 2 * HDIM) ((float*)sh_h)[tid] = 0.f;
    if (tid == 0) {
        asm volatile("mbarrier.init.shared.b64 [%0], %1;" :: "r"(m_base),     "r"(1) : "memory");
        asm volatile("mbarrier.init.shared.b64 [%0], %1;" :: "r"(m_base + 8), "r"(1) : "memory");
    }
    __syncthreads();
    asm volatile("barrier.cluster.arrive.aligned;" ::: "memory");
    asm volatile("barrier.cluster.wait.aligned;"   ::: "memory");

    int par0 = 0, par1 = 0;
    int cur = 0;
    float h_prev = 0.f;
    float gxr = 0.f, gxz = 0.f, gxn = 0.f;
    if (prod) {
        gxr = __ldg(gx + j);
        gxz = __ldg(gx + HDIM + j);
        gxn = __ldg(gx + 2 * HDIM + j);
    }

    for (int t = 0; t < T; t++) {
        const int nxt = cur ^ 1;

        // announce this step's fill phase on local mbar[nxt] (arrive=1, tx=1024B)
        if (tid == 0 && t + 1 < T) {
            asm volatile("mbarrier.arrive.expect_tx.shared.b64 _, [%0], %1;"
                         :: "r"(m_base + (uint32_t)(nxt * 8)), "r"(1024) : "memory");
        }

        if (t > 0) {
            if (cur == 0) { mbar_wait_cluster(m_base,     par0); par0 ^= 1; }
            else          { mbar_wait_cluster(m_base + 8, par1); par1 ^= 1; }
        }

        // prefetch next step's gx
        float ngr = 0.f, ngz = 0.f, ngn = 0.f;
        if (prod && t + 1 < T) {
            const float* g = gx + (size_t)(t + 1) * G3;
            ngr = __ldg(g + j); ngz = __ldg(g + HDIM + j); ngn = __ldg(g + 2 * HDIM + j);
        }

        // matvec slice: 64 MACs as 32 f32x2 FMAs
        const uint32_t haddr = h_base + (uint32_t)(cur * HDIM * 4 + ksl * 256);
        ull c0 = 0ull, c1 = 0ull, c2 = 0ull, c3 = 0ull;
        #pragma unroll
        for (int i = 0; i < 8; i++) {
            ull h0, h1, h2, h3;
            LDS_2U64(h0, h1, haddr + i * 32);
            LDS_2U64(h2, h3, haddr + i * 32 + 16);
            FMA2(c0, ww[4 * i + 0], h0);
            FMA2(c1, ww[4 * i + 1], h1);
            FMA2(c2, ww[4 * i + 2], h2);
            FMA2(c3, ww[4 * i + 3], h3);
        }
        ull cs, cs2, ct;
        ADD2(cs, c0, c1);
        ADD2(cs2, c2, c3);
        ADD2(ct, cs, cs2);
        float lo, hi;
        UNPACK2(lo, hi, ct);
        float acc = lo + hi;
        acc += __shfl_xor_sync(0xffffffffu, acc, 1);
        acc += __shfl_xor_sync(0xffffffffu, acc, 2);
        const int b16 = lane & 16;
        float zacc = __shfl_sync(0xffffffffu, acc, b16 + 4);
        float nacc = __shfl_sync(0xffffffffu, acc, b16 + 8);

        if (prod) {
            float r = sigm(gxr + b_r + acc);
            float z = sigm(gxz + b_z + zacc);
            float n = tanh_fast(gxn + r * (b_n + nacc));
            float h_new = (1.f - z) * n + z * h_prev;
            h_prev = h_new;
            HS[(size_t)t * HDIM + j] = h_new;
            stage[jl] = h_new;
        }
        __syncthreads();   // stage complete; sh_h[cur] reads complete

        if (tid < GRU_CLUSTER && t + 1 < T) {
            asm volatile("fence.proxy.async.shared::cta;" ::: "memory");
            const uint32_t dst  = peer_h[tid] + (uint32_t)(nxt * 1024 + rank * 128);
            const uint32_t mbar = peer_m[tid] + (uint32_t)(nxt * 8);
            asm volatile(
                "cp.async.bulk.shared::cluster.shared::cta.mbarrier::complete_tx::bytes "
                "[%0], [%1], %2, [%3];"
                :: "r"(dst), "r"(s_base), "r"(128), "r"(mbar) : "memory");
        }
        gxr = ngr; gxz = ngz; gxn = ngn;
        cur = nxt;
    }

    asm volatile("barrier.cluster.arrive.aligned;" ::: "memory");
    asm volatile("barrier.cluster.wait.aligned;"   ::: "memory");
}

// ---------------- claim-gated sentence states ------------------------------
__global__ void gate_kernel(const float* __restrict__ HS,
                            const float* __restrict__ gate_s_w,
                            float* __restrict__ hsg)
{
    int row = blockIdx.x * blockDim.y + threadIdx.y;
    int lane = threadIdx.x;
    const float* h = HS + (size_t)row * HDIM;
    float s = 0.f;
    for (int k = lane; k < HDIM; k += 32) s += h[k] * gate_s_w[k];
    s = warp_sum(s);
    float g = sigm(s + g_c0[0]);
    for (int k = lane; k < HDIM; k += 32) {
        float hv = h[k];
        hsg[(size_t)row * HDIM + k] = g * hv + (1.f - g) * g_hc[k];
    }
}

// ---------------- row softmax over S ---------------------------------------
__global__ void softmax_rows(float* __restrict__ S, float* __restrict__ rinv)
{
    __shared__ float sm[8];
    __shared__ float s_bcast;
    const int row = blockIdx.x;
    float* p = S + (size_t)row * LSQ;
    const int tid = threadIdx.x;   // 256

    float m = -1e30f;
    for (int j = tid; j < LSQ; j += 256) m = fmaxf(m, p[j]);
    m = warp_max(m);
    if ((tid & 31) == 0) sm[tid >> 5] = m;
    __syncthreads();
    if (tid == 0) {
        float v = sm[0];
        for (int i = 1; i < 8; i++) v = fmaxf(v, sm[i]);
        s_bcast = v;
    }
    __syncthreads();
    const float bm = s_bcast;

    float s = 0.f;
    for (int j = tid; j < LSQ; j += 256) {
        float e = __expf(p[j] - bm);
        p[j] = e;
        s += e;
    }
    s = warp_sum(s);
    if ((tid & 31) == 0) sm[tid >> 5] = s;
    __syncthreads();
    if (tid == 0) {
        float v = 0.f;
        for (int i = 0; i < 8; i++) v += sm[i];
        rinv[row] = 1.f / v;
    }
}

// ---------------- transpose hs_g [8192,256] -> [256,8192] ------------------
__global__ void transpose_k(const float* __restrict__ in, float* __restrict__ out)
{
    __shared__ float t[32][33];
    int x = blockIdx.x * 32 + threadIdx.x;
    int y0 = blockIdx.y * 32;
    for (int i = threadIdx.y; i < 32; i += 8)
        t[i][threadIdx.x] = in[(size_t)(y0 + i) * HDIM + x];
    __syncthreads();
    int ox = blockIdx.y * 32 + threadIdx.x;
    int oy = blockIdx.x * 32;
    for (int i = threadIdx.y; i < 32; i += 8)
        out[(size_t)(oy + i) * LSQ + ox] = t[threadIdx.x][i];
}

// ---------------- concat [HS | h_apo] --------------------------------------
__global__ void concat_kernel(const float* __restrict__ HS,
                              const float* __restrict__ hapo,
                              float* __restrict__ cat)
{
    int idx = blockIdx.x * blockDim.x + threadIdx.x;
    int i = idx >> 9, d = idx & 511;
    cat[idx] = (d < HDIM) ? HS[(size_t)i * HDIM + d]
                          : hapo[(size_t)i * HDIM + d - HDIM];
}

// ---------------- feat3 = [h_til, hc*h_til, |hc - h_til|] ------------------
__global__ void feat_kernel(const float* __restrict__ htil, float* __restrict__ feat)
{
    int idx = blockIdx.x * blockDim.x + threadIdx.x;
    int i = idx / 768, d = idx % 768;
    int dd = d & 255;
    float ht = htil[(size_t)i * HDIM + dd];
    float hv = g_hc[dd];
    float v;
    if (d < 256) v = ht;
    else if (d < 512) v = hv * ht;
    else v = fabsf(hv - ht);
    feat[idx] = v;
}

// ---------------- entailment score per row ---------------------------------
__global__ void ent_kernel(const float* __restrict__ hcs,
                           const float* __restrict__ w,
                           const float* __restrict__ b,
                           float* __restrict__ e)
{
    int row = blockIdx.x * blockDim.y + threadIdx.y;
    int lane = threadIdx.x;
    const float* h = hcs + (size_t)row * HDIM;
    float s = 0.f;
    for (int k = lane; k < HDIM; k += 32) s += h[k] * w[k];
    s = warp_sum(s);
    if (lane == 0) e[row] = tanhf(s + b[0]);
}

// ---------------- softmax(e) scalars + zero hcS ----------------------------
__global__ void reduce_e_kernel(const float* __restrict__ e)
{
    __shared__ float sm[32];
    __shared__ float s_max;
    int tid = threadIdx.x;  // 1024
    float m = -1e30f;
    for (int i = tid; i < LSQ; i += 1024) m = fmaxf(m, e[i]);
    m = warp_max(m);
    if ((tid & 31) == 0) sm[tid >> 5] = m;
    __syncthreads();
    if (tid == 0) {
        float v = sm[0];
        for (int i = 1; i < 32; i++) v = fmaxf(v, sm[i]);
        s_max = v;
        g_red[0] = v;
    }
    __syncthreads();
    float mx = s_max;
    float s = 0.f;
    for (int i = tid; i < LSQ; i += 1024) s += __expf(e[i] - mx);
    s = warp_sum(s);
    if ((tid & 31) == 0) sm[tid >> 5] = s;
    __syncthreads();
    if (tid == 0) {
        float v = 0.f;
        for (int i = 0; i < 32; i++) v += sm[i];
        g_red[1] = v;
    }
    if (tid < HDIM) g_hcS[tid] = 0.f;
}

// ---------------- h_c_S = sum_i a_i * h_c_s[i] -----------------------------
__global__ void weighted_sum_kernel(const float* __restrict__ e,
                                    const float* __restrict__ hcs)
{
    __shared__ float sa[256];
    int d = threadIdx.x;
    int r0 = blockIdx.x * 256;
    float mx = g_red[0], inv = 1.f / g_red[1];
    sa[d] = __expf(e[r0 + d] - mx) * inv;
    __syncthreads();
    float acc = 0.f;
    for (int rr = 0; rr < 256; rr++)
        acc += sa[rr] * hcs[(size_t)(r0 + rr) * HDIM + d];
    atomicAdd(&g_hcS[d], acc);
}

// ---------------- final logits + softmax -----------------------------------
__global__ void final_kernel(const float* __restrict__ fw,
                             const float* __restrict__ fb,
                             float* __restrict__ out)
{
    __shared__ float lg[3];
    int warp = threadIdx.x >> 5, lane = threadIdx.x & 31;
    if (warp < 3) {
        float s = 0.f;
        for (int k = lane; k < HDIM; k += 32) s += g_hcS[k] * fw[warp * HDIM + k];
        s = warp_sum(s);
        if (lane == 0) lg[warp] = s + fb[warp];
    }
    __syncthreads();
    if (threadIdx.x == 0) {
        float m = fmaxf(lg[0], fmaxf(lg[1], lg[2]));
        float e0 = __expf(lg[0] - m), e1 = __expf(lg[1] - m), e2 = __expf(lg[2] - m);
        float inv = 1.f / (e0 + e1 + e2);
        out[0] = e0 * inv; out[1] = e1 * inv; out[2] = e2 * inv;
    }
}

// ---------------- launch ---------------------------------------------------
extern "C" void kernel_launch(void* const* d_in, const int* in_sizes, int n_in,
                              void* d_out, int out_size)
{
    const float* claim     = (const float*)d_in[0];
    const float* sentences = (const float*)d_in[1];
    const float* c_wih     = (const float*)d_in[2];
    const float* c_bih     = (const float*)d_in[4];
    const float* c_bhh     = (const float*)d_in[5];
    const float* s_wih     = (const float*)d_in[6];
    const float* s_whh     = (const float*)d_in[7];
    const float* s_bih     = (const float*)d_in[8];
    const float* s_bhh     = (const float*)d_in[9];
    const float* gate_s_w  = (const float*)d_in[10];
    const float* gate_c_w  = (const float*)d_in[11];
    const float* atten_c_w = (const float*)d_in[12];
    const float* atten_c_b = (const float*)d_in[13];
    // atten_s_w/b (14,15): per-row constant in scores -> cancels in softmax
    const float* ext_w     = (const float*)d_in[16];
    const float* ext_b     = (const float*)d_in[17];
    const float* joint_w   = (const float*)d_in[18];
    const float* ent_w     = (const float*)d_in[19];
    const float* ent_b     = (const float*)d_in[20];
    const float* final_w   = (const float*)d_in[21];
    const float* final_b   = (const float*)d_in[22];
    float* out = (float*)d_out;

    float *p_gx, *p_HS, *p_hsg, *p_hsgT, *p_A, *p_S, *p_rinv, *p_hapo,
          *p_cat, *p_htil, *p_feat, *p_hcs, *p_e, *p_cvec;
    cudaGetSymbolAddress((void**)&p_gx,   g_gx);
    cudaGetSymbolAddress((void**)&p_HS,   g_HS);
    cudaGetSymbolAddress((void**)&p_hsg,  g_hsg);
    cudaGetSymbolAddress((void**)&p_hsgT, g_hsgT);
    cudaGetSymbolAddress((void**)&p_A,    g_A);
    cudaGetSymbolAddress((void**)&p_S,    g_S);
    cudaGetSymbolAddress((void**)&p_rinv, g_rinv);
    cudaGetSymbolAddress((void**)&p_hapo, g_hapo);
    cudaGetSymbolAddress((void**)&p_cat,  g_cat);
    cudaGetSymbolAddress((void**)&p_htil, g_htil);
    cudaGetSymbolAddress((void**)&p_feat, g_feat);
    cudaGetSymbolAddress((void**)&p_hcs,  g_hcs);
    cudaGetSymbolAddress((void**)&p_e,    g_e);
    cudaGetSymbolAddress((void**)&p_cvec, g_cvec);

    // 0: dummy (aligns ncu window: launch index 3 = gru_kernel)
    dummy_kernel<<<1, 32>>>();

    // 1: claim GRU + c0 + cvec
    claim_kernel<<<1, 768>>>(claim, c_wih, c_bih, c_bhh, gate_c_w, joint_w);

    // 2: gx = sentences @ s_wih^T + s_bih   (K=300)
    sgemm128<<<dim3(G3 / 128, LSQ / 128), 256>>>(
        sentences, EDIM, s_wih, EDIM, p_gx, G3, LSQ, G3, EDIM, s_bih);

    // 3: sentence GRU (profiled this round)
    gru_kernel<<<GRU_CLUSTER, 512>>>(s_whh, s_bhh, p_gx, p_HS, LSQ);

    // 4: claim-gated states
    gate_kernel<<<LSQ / 8, dim3(32, 8)>>>(p_HS, gate_s_w, p_hsg);

    // A = hs_g @ atten_c_w^T + atten_c_b
    sgemm_db<0><<<dim3(HDIM / 128, LSQ / 128), 256>>>(
        p_hsg, HDIM, atten_c_w, HDIM, p_A, HDIM, LSQ, HDIM, HDIM, atten_c_b, nullptr);

    // S = A @ hs_g^T
    sgemm_db<0><<<dim3(LSQ / 128, LSQ / 128), 256>>>(
        p_A, HDIM, p_hsg, HDIM, p_S, LSQ, LSQ, LSQ, HDIM, nullptr, nullptr);

    // row softmax (unnormalized exp; 1/rowsum)
    softmax_rows<<<LSQ, 256>>>(p_S, p_rinv);

    // hs_g^T
    transpose_k<<<dim3(HDIM / 32, LSQ / 32), dim3(32, 8)>>>(p_hsg, p_hsgT);

    // h_apo = diag(rinv) * P @ hs_g
    sgemm_db<0><<<dim3(HDIM / 128, LSQ / 128), 256>>>(
        p_S, LSQ, p_hsgT, LSQ, p_hapo, HDIM, LSQ, HDIM, LSQ, nullptr, p_rinv);

    // h_til = tanh([HS | h_apo] @ ext_w^T + ext_b)
    concat_kernel<<<(LSQ * 512) / 1024, 1024>>>(p_HS, p_hapo, p_cat);
    sgemm_db<1><<<dim3(HDIM / 128, LSQ / 128), 256>>>(
        p_cat, 2 * HDIM, ext_w, 2 * HDIM, p_htil, HDIM, LSQ, HDIM, 2 * HDIM, ext_b, nullptr);

    // h_c_s = tanh(cvec + feat3 @ joint_w[:,256:]^T)
    feat_kernel<<<(LSQ * 768) / 1024, 1024>>>(p_htil, p_feat);
    sgemm_db<1><<<dim3(HDIM / 128, LSQ / 128), 256>>>(
        p_feat, 3 * HDIM, joint_w + HDIM, 4 * HDIM, p_hcs, HDIM, LSQ, HDIM, 3 * HDIM,
        p_cvec, nullptr);

    // entailment softmax-weighted pooling + final
    ent_kernel<<<LSQ / 8, dim3(32, 8)>>>(p_hcs, ent_w, ent_b, p_e);
    reduce_e_kernel<<<1, 1024>>>(p_e);
    weighted_sum_kernel<<<LSQ / 256, 256>>>(p_e, p_hcs);
    final_kernel<<<1, 128>>>(final_w, final_b, out);
}

// round 7
// speedup vs baseline: 1.0523x; 1.0523x over previous
#include <cuda_runtime.h>
#include <math.h>
#include <stdint.h>

#define LSQ   8192
#define EDIM  300
#define HDIM  256
#define G3    768
#define GRU_CLUSTER 8

typedef unsigned long long ull;

// ---------------- scratch (static device allocations; no cudaMalloc) -------
__device__ float g_gx  [LSQ * G3];
__device__ float g_HS  [LSQ * HDIM];
__device__ float g_hsg [LSQ * HDIM];
__device__ float g_hsgT[HDIM * LSQ];
__device__ float g_A   [LSQ * HDIM];
__device__ float g_S   [67108864];        // 8192*8192
__device__ float g_rinv[LSQ];
__device__ float g_hapo[LSQ * HDIM];
__device__ float g_cat [LSQ * 2 * HDIM];
__device__ float g_htil[LSQ * HDIM];
__device__ float g_feat[LSQ * 3 * HDIM];
__device__ float g_hcs [LSQ * HDIM];
__device__ float g_e   [LSQ];
__device__ float g_red [2];
__device__ float g_hc  [HDIM];
__device__ float g_c0  [1];
__device__ float g_cvec[HDIM];
__device__ float g_hcS [HDIM];

// ---------------- helpers --------------------------------------------------
__device__ __forceinline__ float sigm(float x) { return 1.f / (1.f + __expf(-x)); }
__device__ __forceinline__ float tanh_fast(float x) {
    float e = __expf(-2.f * x);
    return (1.f - e) / (1.f + e);
}
__device__ __forceinline__ float warp_sum(float v) {
    #pragma unroll
    for (int o = 16; o; o >>= 1) v += __shfl_xor_sync(0xffffffffu, v, o);
    return v;
}
__device__ __forceinline__ float warp_max(float v) {
    #pragma unroll
    for (int o = 16; o; o >>= 1) v = fmaxf(v, __shfl_xor_sync(0xffffffffu, v, o));
    return v;
}
__device__ __forceinline__ uint32_t smem_u32(const void* p) {
    return (uint32_t)__cvta_generic_to_shared(p);
}
// NON-SLEEPING spin wait: test_wait polls (~149 cyc/poll), never suspends.
__device__ __forceinline__ void mbar_wait_spin(uint32_t addr, int parity) {
    asm volatile(
        "{\n\t"
        ".reg .pred P;\n\t"
        "SPIN_%=:\n\t"
        "mbarrier.test_wait.parity.acquire.cluster.shared::cta.b64 P, [%0], %1;\n\t"
        "@!P bra.uni SPIN_%=;\n\t"
        "}"
        :: "r"(addr), "r"(parity) : "memory");
}

// packed f32x2 ops
#define FMA2(d, a, b)  asm("fma.rn.f32x2 %0, %1, %2, %0;" : "+l"(d) : "l"(a), "l"(b))
#define ADD2(d, a, b)  asm("add.rn.f32x2 %0, %1, %2;" : "=l"(d) : "l"(a), "l"(b))
#define PACK2(d, lo, hi)   asm("mov.b64 %0, {%1, %2};" : "=l"(d) : "f"(lo), "f"(hi))
#define UNPACK2(lo, hi, s) asm("mov.b64 {%0, %1}, %2;" : "=f"(lo), "=f"(hi) : "l"(s))
#define LDS_2U64(a, b, addr) \
    asm volatile("ld.shared.v2.b64 {%0, %1}, [%2];" : "=l"(a), "=l"(b) : "r"(addr))

// ---------------- dummy: shifts ncu capture window (index 3 = gru) ---------
__global__ void dummy_kernel() {}

// ---------------- pipelined f32x2 SGEMM: C = act(rscale[m]*(A@B^T)+bias[n])
template <int ACT>
__global__ void __launch_bounds__(256)
sgemm_db(const float* __restrict__ A, int lda,
         const float* __restrict__ B, int ldb,
         float* __restrict__ C, int ldc,
         int M, int N, int K,
         const float* __restrict__ bias,
         const float* __restrict__ rscale)
{
    __shared__ float As[2][8][128];
    __shared__ float Bs[2][8][128];
    const int bm = blockIdx.y * 128, bn = blockIdx.x * 128;
    const int tid = threadIdx.x;
    const int ty = tid >> 4, tx = tid & 15;
    const int lr = tid >> 1;
    const int lc4 = (tid & 1) * 4;
    const int KT = K >> 3;

    const float* Aptr = A + (size_t)(bm + lr) * lda + lc4;
    const float* Bptr = B + (size_t)(bn + lr) * ldb + lc4;

    float4 ra = *(const float4*)Aptr;
    float4 rb = *(const float4*)Bptr;
    As[0][lc4 + 0][lr] = ra.x; As[0][lc4 + 1][lr] = ra.y;
    As[0][lc4 + 2][lr] = ra.z; As[0][lc4 + 3][lr] = ra.w;
    Bs[0][lc4 + 0][lr] = rb.x; Bs[0][lc4 + 1][lr] = rb.y;
    Bs[0][lc4 + 2][lr] = rb.z; Bs[0][lc4 + 3][lr] = rb.w;
    if (KT > 1) { ra = *(const float4*)(Aptr + 8); rb = *(const float4*)(Bptr + 8); }
    __syncthreads();

    ull acc[8][4];
    #pragma unroll
    for (int i = 0; i < 8; i++)
        #pragma unroll
        for (int j = 0; j < 4; j++) acc[i][j] = 0ull;

    const uint32_t asb = smem_u32(&As[0][0][0]);
    const uint32_t bsb = smem_u32(&Bs[0][0][0]);

    for (int kt = 0; kt < KT; kt++) {
        const int buf = kt & 1;
        if (kt + 1 < KT) {
            const int nb = buf ^ 1;
            As[nb][lc4 + 0][lr] = ra.x; As[nb][lc4 + 1][lr] = ra.y;
            As[nb][lc4 + 2][lr] = ra.z; As[nb][lc4 + 3][lr] = ra.w;
            Bs[nb][lc4 + 0][lr] = rb.x; Bs[nb][lc4 + 1][lr] = rb.y;
            Bs[nb][lc4 + 2][lr] = rb.z; Bs[nb][lc4 + 3][lr] = rb.w;
        }
        if (kt + 2 < KT) {
            ra = *(const float4*)(Aptr + (size_t)(kt + 2) * 8);
            rb = *(const float4*)(Bptr + (size_t)(kt + 2) * 8);
        }
        const uint32_t aoff = asb + (uint32_t)(buf * 4096 + ty * 32);
        const uint32_t boff = bsb + (uint32_t)(buf * 4096 + tx * 32);
        #pragma unroll
        for (int kk = 0; kk < 8; kk++) {
            ull b0, b1, b2, b3;
            LDS_2U64(b0, b1, boff + kk * 512);
            LDS_2U64(b2, b3, boff + kk * 512 + 16);
            float4 av0 = *(const float4*)((const char*)As + (aoff - asb) + kk * 512);
            float4 av1 = *(const float4*)((const char*)As + (aoff - asb) + kk * 512 + 16);
            ull a2[8];
            PACK2(a2[0], av0.x, av0.x); PACK2(a2[1], av0.y, av0.y);
            PACK2(a2[2], av0.z, av0.z); PACK2(a2[3], av0.w, av0.w);
            PACK2(a2[4], av1.x, av1.x); PACK2(a2[5], av1.y, av1.y);
            PACK2(a2[6], av1.z, av1.z); PACK2(a2[7], av1.w, av1.w);
            #pragma unroll
            for (int i = 0; i < 8; i++) {
                FMA2(acc[i][0], a2[i], b0);
                FMA2(acc[i][1], a2[i], b1);
                FMA2(acc[i][2], a2[i], b2);
                FMA2(acc[i][3], a2[i], b3);
            }
        }
        __syncthreads();
    }

    float4 bz0 = make_float4(0.f, 0.f, 0.f, 0.f), bz1 = bz0;
    if (bias) {
        bz0 = *(const float4*)&bias[bn + tx * 8];
        bz1 = *(const float4*)&bias[bn + tx * 8 + 4];
    }
    #pragma unroll
    for (int i = 0; i < 8; i++) {
        const int m = bm + ty * 8 + i;
        const float rs = rscale ? rscale[m] : 1.f;
        float4 o0, o1;
        UNPACK2(o0.x, o0.y, acc[i][0]); UNPACK2(o0.z, o0.w, acc[i][1]);
        UNPACK2(o1.x, o1.y, acc[i][2]); UNPACK2(o1.z, o1.w, acc[i][3]);
        o0.x = o0.x * rs + bz0.x; o0.y = o0.y * rs + bz0.y;
        o0.z = o0.z * rs + bz0.z; o0.w = o0.w * rs + bz0.w;
        o1.x = o1.x * rs + bz1.x; o1.y = o1.y * rs + bz1.y;
        o1.z = o1.z * rs + bz1.z; o1.w = o1.w * rs + bz1.w;
        if (ACT == 1) {
            o0.x = tanh_fast(o0.x); o0.y = tanh_fast(o0.y);
            o0.z = tanh_fast(o0.z); o0.w = tanh_fast(o0.w);
            o1.x = tanh_fast(o1.x); o1.y = tanh_fast(o1.y);
            o1.z = tanh_fast(o1.z); o1.w = tanh_fast(o1.w);
        }
        float* cp = C + (size_t)m * ldc + bn + tx * 8;
        *(float4*)cp = o0;
        *(float4*)(cp + 4) = o1;
    }
}

// ---------------- fallback SGEMM for K=300 (gx projection) -----------------
__global__ void __launch_bounds__(256)
sgemm128(const float* __restrict__ A, int lda,
         const float* __restrict__ B, int ldb,
         float* __restrict__ C, int ldc,
         int M, int N, int K,
         const float* __restrict__ bias)
{
    __shared__ float As[8][128];
    __shared__ float Bs[8][128];
    const int bm = blockIdx.y * 128, bn = blockIdx.x * 128;
    const int tid = threadIdx.x;
    const int ty = tid / 16, tx = tid % 16;
    const int lr = tid >> 1;
    const int lc = (tid & 1) * 4;

    float acc[8][8];
    #pragma unroll
    for (int i = 0; i < 8; i++)
        #pragma unroll
        for (int j = 0; j < 8; j++) acc[i][j] = 0.f;

    for (int k0 = 0; k0 < K; k0 += 8) {
        const float* Ap = A + (size_t)(bm + lr) * lda + k0 + lc;
        const float* Bp = B + (size_t)(bn + lr) * ldb + k0 + lc;
        #pragma unroll
        for (int i = 0; i < 4; i++) {
            As[lc + i][lr] = (k0 + lc + i < K) ? Ap[i] : 0.f;
            Bs[lc + i][lr] = (k0 + lc + i < K) ? Bp[i] : 0.f;
        }
        __syncthreads();
        #pragma unroll
        for (int kk = 0; kk < 8; kk++) {
            float4 a0 = *(const float4*)&As[kk][ty * 8];
            float4 a1 = *(const float4*)&As[kk][ty * 8 + 4];
            float4 b0 = *(const float4*)&Bs[kk][tx * 8];
            float4 b1 = *(const float4*)&Bs[kk][tx * 8 + 4];
            float av[8] = {a0.x, a0.y, a0.z, a0.w, a1.x, a1.y, a1.z, a1.w};
            float bv[8] = {b0.x, b0.y, b0.z, b0.w, b1.x, b1.y, b1.z, b1.w};
            #pragma unroll
            for (int i = 0; i < 8; i++)
                #pragma unroll
                for (int j = 0; j < 8; j++)
                    acc[i][j] = fmaf(av[i], bv[j], acc[i][j]);
        }
        __syncthreads();
    }

    #pragma unroll
    for (int i = 0; i < 8; i++) {
        int m = bm + ty * 8 + i;
        #pragma unroll
        for (int j = 0; j < 8; j++) {
            int n = bn + tx * 8 + j;
            C[(size_t)m * ldc + n] = acc[i][j] + (bias ? bias[n] : 0.f);
        }
    }
}

// ---------------- claim GRU (L=1) + c0 + cvec ------------------------------
__global__ void claim_kernel(const float* __restrict__ claim,
                             const float* __restrict__ wih,
                             const float* __restrict__ bih,
                             const float* __restrict__ bhh,
                             const float* __restrict__ gate_c_w,
                             const float* __restrict__ joint_w)
{
    __shared__ float sc[EDIM];
    __shared__ float gx[G3];
    __shared__ float hcs[HDIM];
    int tid = threadIdx.x;  // 768 threads
    for (int k = tid; k < EDIM; k += G3) sc[k] = claim[k];
    __syncthreads();

    float a = 0.f;
    const float* w = wih + (size_t)tid * EDIM;
    for (int k = 0; k < EDIM; k++) a += sc[k] * w[k];
    gx[tid] = a + bih[tid];
    __syncthreads();

    if (tid < HDIM) {
        float r = sigm(gx[tid] + bhh[tid]);
        float z = sigm(gx[HDIM + tid] + bhh[HDIM + tid]);
        float n = tanhf(gx[2 * HDIM + tid] + r * bhh[2 * HDIM + tid]);
        float h = (1.f - z) * n;     // h0 = 0
        hcs[tid] = h;
        g_hc[tid] = h;
    }
    __syncthreads();

    if (tid < 32) {
        float s = 0.f;
        for (int k = tid; k < HDIM; k += 32) s += hcs[k] * gate_c_w[k];
        s = warp_sum(s);
        if (tid == 0) g_c0[0] = s;
    }
    if (tid < HDIM) {
        float s = 0.f;
        const float* jw = joint_w + (size_t)tid * 1024;
        for (int k = 0; k < HDIM; k++) s += hcs[k] * jw[k];
        g_cvec[tid] = s;
    }
}

// ---------------- sentence GRU: 8-CTA cluster, st.async + SPIN wait --------
__global__ void __cluster_dims__(GRU_CLUSTER, 1, 1) __launch_bounds__(512, 1)
gru_kernel(const float* __restrict__ whh,
           const float* __restrict__ bhh,
           const float* __restrict__ gx,
           float* __restrict__ HS, int T)
{
    __shared__ __align__(16) float sh_h[2][HDIM];
    __shared__ __align__(8) unsigned long long mbar2[2];

    const int tid   = threadIdx.x;
    const int lane  = tid & 31;
    const int warp  = tid >> 5;       // 0..15
    const int half  = (lane >> 4);    // 0/1
    const int lane4 = lane & 15;
    const int gate  = lane4 >> 2;     // 0..3 (3 idle)
    const int ksl   = lane4 & 3;
    unsigned rank;
    asm("mov.u32 %0, %%cluster_ctarank;" : "=r"(rank));
    const int j = (int)rank * 32 + warp * 2 + half;
    const bool prod = (lane4 == 0);

    const uint32_t h_base = smem_u32(&sh_h[0][0]);
    const uint32_t m_base = smem_u32(&mbar2[0]);
    const uint32_t mbar_off = m_base - h_base;

    // per-rank DSMEM base of sh_h[0][0]
    uint32_t peer_base[GRU_CLUSTER];
    #pragma unroll
    for (int c = 0; c < GRU_CLUSTER; c++)
        asm("mapa.shared::cluster.u32 %0, %1, %2;" : "=r"(peer_base[c]) : "r"(h_base), "r"(c));

    // weights -> 32 packed f32x2 registers
    ull ww[32];
    if (gate < 3) {
        const float4* wp = reinterpret_cast<const float4*>(
            whh + (size_t)(gate * HDIM + j) * HDIM + ksl * 64);
        #pragma unroll
        for (int i = 0; i < 16; i++) {
            float4 v = wp[i];
            PACK2(ww[2 * i],     v.x, v.y);
            PACK2(ww[2 * i + 1], v.z, v.w);
        }
    } else {
        #pragma unroll
        for (int i = 0; i < 32; i++) ww[i] = 0ull;
    }
    const float b_r = bhh[j];
    const float b_z = bhh[HDIM + j];
    const float b_n = bhh[2 * HDIM + j];

    if (tid < 2 * HDIM) ((float*)sh_h)[tid] = 0.f;
    if (tid == 0) {
        asm volatile("mbarrier.init.shared.b64 [%0], %1;" :: "r"(m_base),     "r"(1) : "memory");
        asm volatile("mbarrier.init.shared.b64 [%0], %1;" :: "r"(m_base + 8), "r"(1) : "memory");
    }
    __syncthreads();
    asm volatile("barrier.cluster.arrive.aligned;" ::: "memory");
    asm volatile("barrier.cluster.wait.aligned;"   ::: "memory");

    int par0 = 0, par1 = 0;
    int cur = 0;
    float h_prev = 0.f;
    float gxr = 0.f, gxz = 0.f, gxn = 0.f;
    if (prod) {
        gxr = __ldg(gx + j);
        gxz = __ldg(gx + HDIM + j);
        gxn = __ldg(gx + 2 * HDIM + j);
    }

    for (int t = 0; t < T; t++) {
        const int nxt = cur ^ 1;

        // announce this step's fill phase on local mbar[nxt] (arrive=1, tx=1024B)
        if (tid == 0 && t + 1 < T) {
            asm volatile("mbarrier.arrive.expect_tx.shared.b64 _, [%0], %1;"
                         :: "r"(m_base + (uint32_t)(nxt * 8)), "r"(1024) : "memory");
        }

        if (t > 0) {
            if (cur == 0) { mbar_wait_spin(m_base,     par0); par0 ^= 1; }
            else          { mbar_wait_spin(m_base + 8, par1); par1 ^= 1; }
        }

        // prefetch next step's gx
        float ngr = 0.f, ngz = 0.f, ngn = 0.f;
        if (prod && t + 1 < T) {
            const float* g = gx + (size_t)(t + 1) * G3;
            ngr = __ldg(g + j); ngz = __ldg(g + HDIM + j); ngn = __ldg(g + 2 * HDIM + j);
        }

        // matvec slice: 64 MACs as 32 f32x2 FMAs
        const uint32_t haddr = h_base + (uint32_t)(cur * HDIM * 4 + ksl * 256);
        ull c0 = 0ull, c1 = 0ull, c2 = 0ull, c3 = 0ull;
        #pragma unroll
        for (int i = 0; i < 8; i++) {
            ull h0, h1, h2, h3;
            LDS_2U64(h0, h1, haddr + i * 32);
            LDS_2U64(h2, h3, haddr + i * 32 + 16);
            FMA2(c0, ww[4 * i + 0], h0);
            FMA2(c1, ww[4 * i + 1], h1);
            FMA2(c2, ww[4 * i + 2], h2);
            FMA2(c3, ww[4 * i + 3], h3);
        }
        ull cs, cs2, ct;
        ADD2(cs, c0, c1);
        ADD2(cs2, c2, c3);
        ADD2(ct, cs, cs2);
        float lo, hi;
        UNPACK2(lo, hi, ct);
        float acc = lo + hi;
        acc += __shfl_xor_sync(0xffffffffu, acc, 1);
        acc += __shfl_xor_sync(0xffffffffu, acc, 2);
        const int b16 = lane & 16;
        float zacc = __shfl_sync(0xffffffffu, acc, b16 + 4);
        float nacc = __shfl_sync(0xffffffffu, acc, b16 + 8);

        if (prod) {
            float r = sigm(gxr + b_r + acc);
            float z = sigm(gxz + b_z + zacc);
            float n = tanh_fast(gxn + r * (b_n + nacc));
            float h_new = (1.f - z) * n + z * h_prev;
            h_prev = h_new;
            HS[(size_t)t * HDIM + j] = h_new;
            if (t + 1 < T) {
                const uint32_t hoff = (uint32_t)(nxt * HDIM * 4 + j * 4);
                const uint32_t moff = mbar_off + (uint32_t)(nxt * 8);
                const uint32_t hbits = __float_as_uint(h_new);
                #pragma unroll
                for (int c = 0; c < GRU_CLUSTER; c++) {
                    asm volatile(
                        "st.async.shared::cluster.mbarrier::complete_tx::bytes.b32 [%0], %1, [%2];"
                        :: "r"(peer_base[c] + hoff), "r"(hbits), "r"(peer_base[c] + moff)
                        : "memory");
                }
            }
        }
        gxr = ngr; gxz = ngz; gxn = ngn;
        cur = nxt;
    }

    asm volatile("barrier.cluster.arrive.aligned;" ::: "memory");
    asm volatile("barrier.cluster.wait.aligned;"   ::: "memory");
}

// ---------------- claim-gated sentence states ------------------------------
__global__ void gate_kernel(const float* __restrict__ HS,
                            const float* __restrict__ gate_s_w,
                            float* __restrict__ hsg)
{
    int row = blockIdx.x * blockDim.y + threadIdx.y;
    int lane = threadIdx.x;
    const float* h = HS + (size_t)row * HDIM;
    float s = 0.f;
    for (int k = lane; k < HDIM; k += 32) s += h[k] * gate_s_w[k];
    s = warp_sum(s);
    float g = sigm(s + g_c0[0]);
    for (int k = lane; k < HDIM; k += 32) {
        float hv = h[k];
        hsg[(size_t)row * HDIM + k] = g * hv + (1.f - g) * g_hc[k];
    }
}

// ---------------- row softmax over S ---------------------------------------
__global__ void softmax_rows(float* __restrict__ S, float* __restrict__ rinv)
{
    __shared__ float sm[8];
    __shared__ float s_bcast;
    const int row = blockIdx.x;
    float* p = S + (size_t)row * LSQ;
    const int tid = threadIdx.x;   // 256

    float m = -1e30f;
    for (int j = tid; j < LSQ; j += 256) m = fmaxf(m, p[j]);
    m = warp_max(m);
    if ((tid & 31) == 0) sm[tid >> 5] = m;
    __syncthreads();
    if (tid == 0) {
        float v = sm[0];
        for (int i = 1; i < 8; i++) v = fmaxf(v, sm[i]);
        s_bcast = v;
    }
    __syncthreads();
    const float bm = s_bcast;

    float s = 0.f;
    for (int j = tid; j < LSQ; j += 256) {
        float e = __expf(p[j] - bm);
        p[j] = e;
        s += e;
    }
    s = warp_sum(s);
    if ((tid & 31) == 0) sm[tid >> 5] = s;
    __syncthreads();
    if (tid == 0) {
        float v = 0.f;
        for (int i = 0; i < 8; i++) v += sm[i];
        rinv[row] = 1.f / v;
    }
}

// ---------------- transpose hs_g [8192,256] -> [256,8192] ------------------
__global__ void transpose_k(const float* __restrict__ in, float* __restrict__ out)
{
    __shared__ float t[32][33];
    int x = blockIdx.x * 32 + threadIdx.x;
    int y0 = blockIdx.y * 32;
    for (int i = threadIdx.y; i < 32; i += 8)
        t[i][threadIdx.x] = in[(size_t)(y0 + i) * HDIM + x];
    __syncthreads();
    int ox = blockIdx.y * 32 + threadIdx.x;
    int oy = blockIdx.x * 32;
    for (int i = threadIdx.y; i < 32; i += 8)
        out[(size_t)(oy + i) * LSQ + ox] = t[threadIdx.x][i];
}

// ---------------- concat [HS | h_apo] --------------------------------------
__global__ void concat_kernel(const float* __restrict__ HS,
                              const float* __restrict__ hapo,
                              float* __restrict__ cat)
{
    int idx = blockIdx.x * blockDim.x + threadIdx.x;
    int i = idx >> 9, d = idx & 511;
    cat[idx] = (d < HDIM) ? HS[(size_t)i * HDIM + d]
                          : hapo[(size_t)i * HDIM + d - HDIM];
}

// ---------------- feat3 = [h_til, hc*h_til, |hc - h_til|] ------------------
__global__ void feat_kernel(const float* __restrict__ htil, float* __restrict__ feat)
{
    int idx = blockIdx.x * blockDim.x + threadIdx.x;
    int i = idx / 768, d = idx % 768;
    int dd = d & 255;
    float ht = htil[(size_t)i * HDIM + dd];
    float hv = g_hc[dd];
    float v;
    if (d < 256) v = ht;
    else if (d < 512) v = hv * ht;
    else v = fabsf(hv - ht);
    feat[idx] = v;
}

// ---------------- entailment score per row ---------------------------------
__global__ void ent_kernel(const float* __restrict__ hcs,
                           const float* __restrict__ w,
                           const float* __restrict__ b,
                           float* __restrict__ e)
{
    int row = blockIdx.x * blockDim.y + threadIdx.y;
    int lane = threadIdx.x;
    const float* h = hcs + (size_t)row * HDIM;
    float s = 0.f;
    for (int k = lane; k < HDIM; k += 32) s += h[k] * w[k];
    s = warp_sum(s);
    if (lane == 0) e[row] = tanhf(s + b[0]);
}

// ---------------- softmax(e) scalars + zero hcS ----------------------------
__global__ void reduce_e_kernel(const float* __restrict__ e)
{
    __shared__ float sm[32];
    __shared__ float s_max;
    int tid = threadIdx.x;  // 1024
    float m = -1e30f;
    for (int i = tid; i < LSQ; i += 1024) m = fmaxf(m, e[i]);
    m = warp_max(m);
    if ((tid & 31) == 0) sm[tid >> 5] = m;
    __syncthreads();
    if (tid == 0) {
        float v = sm[0];
        for (int i = 1; i < 32; i++) v = fmaxf(v, sm[i]);
        s_max = v;
        g_red[0] = v;
    }
    __syncthreads();
    float mx = s_max;
    float s = 0.f;
    for (int i = tid; i < LSQ; i += 1024) s += __expf(e[i] - mx);
    s = warp_sum(s);
    if ((tid & 31) == 0) sm[tid >> 5] = s;
    __syncthreads();
    if (tid == 0) {
        float v = 0.f;
        for (int i = 0; i < 32; i++) v += sm[i];
        g_red[1] = v;
    }
    if (tid < HDIM) g_hcS[tid] = 0.f;
}

// ---------------- h_c_S = sum_i a_i * h_c_s[i] -----------------------------
__global__ void weighted_sum_kernel(const float* __restrict__ e,
                                    const float* __restrict__ hcs)
{
    __shared__ float sa[256];
    int d = threadIdx.x;
    int r0 = blockIdx.x * 256;
    float mx = g_red[0], inv = 1.f / g_red[1];
    sa[d] = __expf(e[r0 + d] - mx) * inv;
    __syncthreads();
    float acc = 0.f;
    for (int rr = 0; rr < 256; rr++)
        acc += sa[rr] * hcs[(size_t)(r0 + rr) * HDIM + d];
    atomicAdd(&g_hcS[d], acc);
}

// ---------------- final logits + softmax -----------------------------------
__global__ void final_kernel(const float* __restrict__ fw,
                             const float* __restrict__ fb,
                             float* __restrict__ out)
{
    __shared__ float lg[3];
    int warp = threadIdx.x >> 5, lane = threadIdx.x & 31;
    if (warp < 3) {
        float s = 0.f;
        for (int k = lane; k < HDIM; k += 32) s += g_hcS[k] * fw[warp * HDIM + k];
        s = warp_sum(s);
        if (lane == 0) lg[warp] = s + fb[warp];
    }
    __syncthreads();
    if (threadIdx.x == 0) {
        float m = fmaxf(lg[0], fmaxf(lg[1], lg[2]));
        float e0 = __expf(lg[0] - m), e1 = __expf(lg[1] - m), e2 = __expf(lg[2] - m);
        float inv = 1.f / (e0 + e1 + e2);
        out[0] = e0 * inv; out[1] = e1 * inv; out[2] = e2 * inv;
    }
}

// ---------------- launch ---------------------------------------------------
extern "C" void kernel_launch(void* const* d_in, const int* in_sizes, int n_in,
                              void* d_out, int out_size)
{
    const float* claim     = (const float*)d_in[0];
    const float* sentences = (const float*)d_in[1];
    const float* c_wih     = (const float*)d_in[2];
    const float* c_bih     = (const float*)d_in[4];
    const float* c_bhh     = (const float*)d_in[5];
    const float* s_wih     = (const float*)d_in[6];
    const float* s_whh     = (const float*)d_in[7];
    const float* s_bih     = (const float*)d_in[8];
    const float* s_bhh     = (const float*)d_in[9];
    const float* gate_s_w  = (const float*)d_in[10];
    const float* gate_c_w  = (const float*)d_in[11];
    const float* atten_c_w = (const float*)d_in[12];
    const float* atten_c_b = (const float*)d_in[13];
    // atten_s_w/b (14,15): per-row constant in scores -> cancels in softmax
    const float* ext_w     = (const float*)d_in[16];
    const float* ext_b     = (const float*)d_in[17];
    const float* joint_w   = (const float*)d_in[18];
    const float* ent_w     = (const float*)d_in[19];
    const float* ent_b     = (const float*)d_in[20];
    const float* final_w   = (const float*)d_in[21];
    const float* final_b   = (const float*)d_in[22];
    float* out = (float*)d_out;

    float *p_gx, *p_HS, *p_hsg, *p_hsgT, *p_A, *p_S, *p_rinv, *p_hapo,
          *p_cat, *p_htil, *p_feat, *p_hcs, *p_e, *p_cvec;
    cudaGetSymbolAddress((void**)&p_gx,   g_gx);
    cudaGetSymbolAddress((void**)&p_HS,   g_HS);
    cudaGetSymbolAddress((void**)&p_hsg,  g_hsg);
    cudaGetSymbolAddress((void**)&p_hsgT, g_hsgT);
    cudaGetSymbolAddress((void**)&p_A,    g_A);
    cudaGetSymbolAddress((void**)&p_S,    g_S);
    cudaGetSymbolAddress((void**)&p_rinv, g_rinv);
    cudaGetSymbolAddress((void**)&p_hapo, g_hapo);
    cudaGetSymbolAddress((void**)&p_cat,  g_cat);
    cudaGetSymbolAddress((void**)&p_htil, g_htil);
    cudaGetSymbolAddress((void**)&p_feat, g_feat);
    cudaGetSymbolAddress((void**)&p_hcs,  g_hcs);
    cudaGetSymbolAddress((void**)&p_e,    g_e);
    cudaGetSymbolAddress((void**)&p_cvec, g_cvec);

    // 0: dummy (aligns ncu window: launch index 3 = gru_kernel)
    dummy_kernel<<<1, 32>>>();

    // 1: claim GRU + c0 + cvec
    claim_kernel<<<1, 768>>>(claim, c_wih, c_bih, c_bhh, gate_c_w, joint_w);

    // 2: gx = sentences @ s_wih^T + s_bih   (K=300)
    sgemm128<<<dim3(G3 / 128, LSQ / 128), 256>>>(
        sentences, EDIM, s_wih, EDIM, p_gx, G3, LSQ, G3, EDIM, s_bih);

    // 3: sentence GRU (spin-wait experiment)
    gru_kernel<<<GRU_CLUSTER, 512>>>(s_whh, s_bhh, p_gx, p_HS, LSQ);

    // 4: claim-gated states
    gate_kernel<<<LSQ / 8, dim3(32, 8)>>>(p_HS, gate_s_w, p_hsg);

    // A = hs_g @ atten_c_w^T + atten_c_b
    sgemm_db<0><<<dim3(HDIM / 128, LSQ / 128), 256>>>(
        p_hsg, HDIM, atten_c_w, HDIM, p_A, HDIM, LSQ, HDIM, HDIM, atten_c_b, nullptr);

    // S = A @ hs_g^T
    sgemm_db<0><<<dim3(LSQ / 128, LSQ / 128), 256>>>(
        p_A, HDIM, p_hsg, HDIM, p_S, LSQ, LSQ, LSQ, HDIM, nullptr, nullptr);

    // row softmax (unnormalized exp; 1/rowsum)
    softmax_rows<<<LSQ, 256>>>(p_S, p_rinv);

    // hs_g^T
    transpose_k<<<dim3(HDIM / 32, LSQ / 32), dim3(32, 8)>>>(p_hsg, p_hsgT);

    // h_apo = diag(rinv) * P @ hs_g
    sgemm_db<0><<<dim3(HDIM / 128, LSQ / 128), 256>>>(
        p_S, LSQ, p_hsgT, LSQ, p_hapo, HDIM, LSQ, HDIM, LSQ, nullptr, p_rinv);

    // h_til = tanh([HS | h_apo] @ ext_w^T + ext_b)
    concat_kernel<<<(LSQ * 512) / 1024, 1024>>>(p_HS, p_hapo, p_cat);
    sgemm_db<1><<<dim3(HDIM / 128, LSQ / 128), 256>>>(
        p_cat, 2 * HDIM, ext_w, 2 * HDIM, p_htil, HDIM, LSQ, HDIM, 2 * HDIM, ext_b, nullptr);

    // h_c_s = tanh(cvec + feat3 @ joint_w[:,256:]^T)
    feat_kernel<<<(LSQ * 768) / 1024, 1024>>>(p_htil, p_feat);
    sgemm_db<1><<<dim3(HDIM / 128, LSQ / 128), 256>>>(
        p_feat, 3 * HDIM, joint_w + HDIM, 4 * HDIM, p_hcs, HDIM, LSQ, HDIM, 3 * HDIM,
        p_cvec, nullptr);

    // entailment softmax-weighted pooling + final
    ent_kernel<<<LSQ / 8, dim3(32, 8)>>>(p_hcs, ent_w, ent_b, p_e);
    reduce_e_kernel<<<1, 1024>>>(p_e);
    weighted_sum_kernel<<<LSQ / 256, 256>>>(p_e, p_hcs);
    final_kernel<<<1, 128>>>(final_w, final_b, out);
}